// round 9
// baseline (speedup 1.0000x reference)
#include <cuda_runtime.h>
#include <math.h>

// Problem constants
#define SQ   256          // sequence length
#define BB   64           // batch
#define HH   512          // hidden
#define IND  1024         // F + H
#define BH   (BB*HH)      // 32768
#define SBH  (SQ*BB*HH)   // 8388608
#define OUT_SZ ((size_t)SQ*BB*2*HH)   // 16777216 floats (out region); hidd follows

// ---------------- device scratch (no cudaMalloc allowed) ----------------
__device__ float g_x [SBH];          // embedded input [s][b][f], forward order
__device__ float g_y0[2][SBH];       // layer-0 output sequence per dir
__device__ float g_h0[2][2][BH];     // layer-0 hidden ping-pong [dir][parity]
__device__ float g_h1[2][2][BH];     // layer-1 hidden ping-pong [dir][parity]
__device__ float g_rh[2][2][BH];     // r * h_prev  [layer][dir]
__device__ float g_z [2][2][BH];     // z gate      [layer][dir]
__device__ float g_ps[2][2][BH];     // s-gate input-half preactivation (+bias)

// ---------------- embedding gather ----------------
__global__ void embed_kernel(const int* __restrict__ tok,
                             const float* __restrict__ emb)
{
    int row = blockIdx.x;                         // s*BB + b, 0..16383
    int t = tok[row];
    const float4* src = (const float4*)(emb + (size_t)t * HH);
    float4* dst = (float4*)(g_x + (size_t)row * HH);
    dst[threadIdx.x] = src[threadIdx.x];          // 128 threads * float4 = 512
}

// ---------------- zero initial hidden states ----------------
__global__ void init_kernel()
{
    int i = blockIdx.x * blockDim.x + threadIdx.x;
    if (i < BH) {
        g_h0[0][0][i] = 0.f; g_h0[1][0][i] = 0.f;
        g_h1[0][0][i] = 0.f; g_h1[1][0][i] = 0.f;
    }
}

// ---------------- shared tile buffers ----------------
struct SmemT {
    float As[64][65];   // A panel, transposed: As[kk][m], stride 65 (bank-friendly)
    float Ws[64][33];   // W panel: Ws[kk][c],  stride 33
};

// Accumulate  acc[r][c] += sum_k A[m][k] * W[col][k]  over k in [k_lo, k_lo+nk)
// A: row stride HH (uses local columns [0,nk) of its half)
// W: row base pointer, row stride IND, k offset wk0
__device__ __forceinline__ void gemm_part(
    const float* __restrict__ A,
    const float* __restrict__ W, int wk0,
    int c0, int nk,
    float (&acc)[4][4], SmemT* sm)
{
    const int tid = threadIdx.x;
    const int tr4 = (tid & 15) * 4;   // row base in C
    const int tc4 = (tid >> 4) * 4;   // col base in C

    for (int k0 = 0; k0 < nk; k0 += 64) {
        __syncthreads();
        // ---- stage A panel 64x64 -> As[kk][m] (transposed) ----
        #pragma unroll
        for (int i = 0; i < 8; ++i) {
            int Q  = i * 128 + tid;       // 0..1023 quads
            int m  = Q >> 4;              // 0..63
            int qk = Q & 15;              // 0..15
            float4 v = *(const float4*)(A + (size_t)m * HH + k0 + qk * 4);
            sm->As[qk*4+0][m] = v.x;
            sm->As[qk*4+1][m] = v.y;
            sm->As[qk*4+2][m] = v.z;
            sm->As[qk*4+3][m] = v.w;
        }
        // ---- stage W panel 32x64 -> Ws[kk][c] ----
        #pragma unroll
        for (int i = 0; i < 4; ++i) {
            int Q  = i * 128 + tid;       // 0..511 quads
            int c  = Q >> 4;              // 0..31
            int qk = Q & 15;
            float4 v = *(const float4*)(W + (size_t)(c0 + c) * IND + wk0 + k0 + qk * 4);
            sm->Ws[qk*4+0][c] = v.x;
            sm->Ws[qk*4+1][c] = v.y;
            sm->Ws[qk*4+2][c] = v.z;
            sm->Ws[qk*4+3][c] = v.w;
        }
        __syncthreads();
        // ---- 4x4 register micro-tile over 64 kk ----
        #pragma unroll 16
        for (int kk = 0; kk < 64; ++kk) {
            float a0 = sm->As[kk][tr4+0];
            float a1 = sm->As[kk][tr4+1];
            float a2 = sm->As[kk][tr4+2];
            float a3 = sm->As[kk][tr4+3];
            float w0 = sm->Ws[kk][tc4+0];
            float w1 = sm->Ws[kk][tc4+1];
            float w2 = sm->Ws[kk][tc4+2];
            float w3 = sm->Ws[kk][tc4+3];
            acc[0][0] += a0*w0; acc[0][1] += a0*w1; acc[0][2] += a0*w2; acc[0][3] += a0*w3;
            acc[1][0] += a1*w0; acc[1][1] += a1*w1; acc[1][2] += a1*w2; acc[1][3] += a1*w3;
            acc[2][0] += a2*w0; acc[2][1] += a2*w1; acc[2][2] += a2*w2; acc[2][3] += a2*w3;
            acc[3][0] += a3*w0; acc[3][1] += a3*w1; acc[3][2] += a3*w2; acc[3][3] += a3*w3;
        }
    }
}

// ---------------- phase 1: r,z gates (both halves) + s-gate input half ----------------
// grid = 192 blocks x 128 threads
//   bid <  128 : r/z gates,  layer=bid>>6, dir=(bid>>5)&1, gate=(bid>>4)&1, tile=bid&15
//   bid >= 128 : s input half, layer=(b2>>5)&1, dir=(b2>>4)&1, tile=b2&15
__global__ void __launch_bounds__(128)
rz_kernel(int t,
          const float* __restrict__ Wr, const float* __restrict__ Wz,
          const float* __restrict__ Wsv,
          const float* __restrict__ br, const float* __restrict__ bz,
          const float* __restrict__ bsv)
{
    __shared__ SmemT sm;
    int bid = blockIdx.x;
    int layer, d, gate, tile;
    if (bid < 128) {
        layer = (bid >> 6) & 1;
        d     = (bid >> 5) & 1;
        gate  = (bid >> 4) & 1;   // 0 = r, 1 = z
        tile  =  bid       & 15;
    } else {
        int s2 = bid - 128;
        layer = (s2 >> 5) & 1;
        d     = (s2 >> 4) & 1;
        gate  = 2;                // s-gate input half
        tile  =  s2       & 15;
    }
    if (layer == 0 && t >= SQ) return;   // layer0 active for t = 0..255
    if (layer == 1 && t <  1 ) return;   // layer1 works on u = t-1

    const float* Ain;
    const float* Ah;
    if (layer == 0) {
        int rt = d ? (SQ - 1 - t) : t;           // backward dir reads flipped input
        Ain = g_x + (size_t)rt * BH;
        Ah  = g_h0[d][t & 1];
    } else {
        int u = t - 1;
        Ain = g_y0[d] + (size_t)u * BH;
        Ah  = g_h1[d][u & 1];
    }

    const float* Wg = (gate == 0 ? Wr : (gate == 1 ? Wz : Wsv))
                      + (size_t)(d * 2 + layer) * HH * IND;
    const float* bvec = (gate == 0 ? br : (gate == 1 ? bz : bsv))
                      + (size_t)(d * 2 + layer) * HH;
    int c0 = tile * 32;

    float acc[4][4];
    #pragma unroll
    for (int r = 0; r < 4; ++r)
        #pragma unroll
        for (int c = 0; c < 4; ++c) acc[r][c] = 0.f;

    // input half (k = 0..511)
    gemm_part(Ain, Wg, 0,  c0, HH, acc, &sm);
    // recurrent half (k = 512..1023) only for r,z
    if (gate < 2)
        gemm_part(Ah,  Wg, HH, c0, HH, acc, &sm);

    int tr4 = (threadIdx.x & 15) * 4;
    int tc4 = (threadIdx.x >> 4) * 4;

    if (gate == 0) {            // r -> store r * h_prev
        #pragma unroll
        for (int r = 0; r < 4; ++r)
            #pragma unroll
            for (int c = 0; c < 4; ++c) {
                int m = tr4 + r, col = c0 + tc4 + c;
                float pre = acc[r][c] + bvec[col];
                float rg  = 1.f / (1.f + expf(-pre));
                g_rh[layer][d][m * HH + col] = rg * Ah[m * HH + col];
            }
    } else if (gate == 1) {     // z
        #pragma unroll
        for (int r = 0; r < 4; ++r)
            #pragma unroll
            for (int c = 0; c < 4; ++c) {
                int m = tr4 + r, col = c0 + tc4 + c;
                float pre = acc[r][c] + bvec[col];
                g_z[layer][d][m * HH + col] = 1.f / (1.f + expf(-pre));
            }
    } else {                    // s input-half partial (+ bias)
        #pragma unroll
        for (int r = 0; r < 4; ++r)
            #pragma unroll
            for (int c = 0; c < 4; ++c) {
                int m = tr4 + r, col = c0 + tc4 + c;
                g_ps[layer][d][m * HH + col] = acc[r][c] + bvec[col];
            }
    }
}

// ---------------- phase 2: s recurrent half + gate combine + h update ----------------
// grid = 64 blocks x 128 threads : layer=(bid>>5)&1, dir=(bid>>4)&1, tile=bid&15
__global__ void __launch_bounds__(128)
s_kernel(int t, const float* __restrict__ Wsv, float* __restrict__ dout)
{
    __shared__ SmemT sm;
    int bid   = blockIdx.x;
    int layer = (bid >> 5) & 1;
    int d     = (bid >> 4) & 1;
    int tile  =  bid       & 15;
    if (layer == 0 && t >= SQ) return;
    if (layer == 1 && t <  1 ) return;

    int u = (layer == 0) ? t : (t - 1);          // time index this cell is computing
    const float* Arh = g_rh[layer][d];
    const float* Wg  = Wsv + (size_t)(d * 2 + layer) * HH * IND;
    int c0 = tile * 32;

    int tr4 = (threadIdx.x & 15) * 4;
    int tc4 = (threadIdx.x >> 4) * 4;

    float acc[4][4];
    #pragma unroll
    for (int r = 0; r < 4; ++r)
        #pragma unroll
        for (int c = 0; c < 4; ++c)
            acc[r][c] = g_ps[layer][d][(tr4 + r) * HH + c0 + tc4 + c];

    // recurrent half of s-gate: A = r*h, W columns 512..1023
    gemm_part(Arh, Wg, HH, c0, HH, acc, &sm);

    const float* hp = (layer == 0) ? g_h0[d][u & 1]       : g_h1[d][u & 1];
    float*       hn = (layer == 0) ? g_h0[d][(u + 1) & 1] : g_h1[d][(u + 1) & 1];

    #pragma unroll
    for (int r = 0; r < 4; ++r)
        #pragma unroll
        for (int c = 0; c < 4; ++c) {
            int m = tr4 + r, col = c0 + tc4 + c;
            int idx = m * HH + col;
            float s = tanhf(acc[r][c]);
            float z = g_z[layer][d][idx];
            float h = z * hp[idx] + (1.f - z) * s;
            hn[idx] = h;
            if (layer == 0) {
                g_y0[d][(size_t)u * BH + idx] = h;
                if (u == SQ - 1)   // hidd[dir*2 + 0]
                    dout[OUT_SZ + (size_t)(d * 2 + 0) * BH + idx] = h;
            } else {
                // out[u][b][dir*H + col]  (backward NOT re-flipped, per reference)
                dout[(size_t)u * BB * (2 * HH) + (size_t)m * (2 * HH) + d * HH + col] = h;
                if (u == SQ - 1)   // hidd[dir*2 + 1]
                    dout[OUT_SZ + (size_t)(d * 2 + 1) * BH + idx] = h;
            }
        }
}

// ---------------- launcher (graph-capturable: kernels only) ----------------
extern "C" void kernel_launch(void* const* d_in, const int* in_sizes, int n_in,
                              void* d_out, int out_size)
{
    const int*   tok = (const int*)  d_in[0];
    const float* emb = (const float*)d_in[1];
    const float* Wr  = (const float*)d_in[2];
    const float* Wz  = (const float*)d_in[3];
    const float* Wsv = (const float*)d_in[4];
    const float* br  = (const float*)d_in[5];
    const float* bz  = (const float*)d_in[6];
    const float* bsv = (const float*)d_in[7];
    float* outp = (float*)d_out;

    embed_kernel<<<SQ * BB, 128>>>(tok, emb);
    init_kernel<<<(BH + 255) / 256, 256>>>();

    // global step t: layer0 computes time t (t<256), layer1 computes time t-1 (t>=1)
    for (int t = 0; t <= SQ; ++t) {
        rz_kernel<<<192, 128>>>(t, Wr, Wz, Wsv, br, bz, bsv);
        s_kernel <<< 64, 128>>>(t, Wsv, outp);
    }
}

// round 10
// speedup vs baseline: 1.5001x; 1.5001x over previous
#include <cuda_runtime.h>
#include <math.h>

// Problem constants
#define SQ   256          // sequence length
#define BB   64           // batch
#define HH   512          // hidden
#define IND  1024         // F + H
#define BH   (BB*HH)      // 32768
#define SBH  (SQ*BB*HH)   // 8388608
#define OUT_SZ ((size_t)SQ*BB*2*HH)   // 16777216 floats (out region); hidd follows

// ---------------- device scratch (no cudaMalloc allowed) ----------------
__device__ float g_x [SBH];          // embedded input [s][b][f], forward order
__device__ float g_y0[2][SBH];       // layer-0 output sequence per dir
__device__ float g_h0[2][2][BH];     // layer-0 hidden ping-pong [dir][parity]
__device__ float g_h1[2][2][BH];     // layer-1 hidden ping-pong [dir][parity]
__device__ float g_rh[2][2][BH];     // r * h_prev  [layer][dir]
__device__ float g_z [2][2][BH];     // z gate      [layer][dir]
__device__ float g_ps[2][2][BH];     // s-gate input-half preactivation (+bias)
__device__ float g_sp[2][2][2][BH];  // s-gate recurrent partials [layer][dir][khalf]

// ---------------- embedding gather ----------------
__global__ void embed_kernel(const int* __restrict__ tok,
                             const float* __restrict__ emb)
{
    int row = blockIdx.x;                         // s*BB + b, 0..16383
    int t = tok[row];
    const float4* src = (const float4*)(emb + (size_t)t * HH);
    float4* dst = (float4*)(g_x + (size_t)row * HH);
    dst[threadIdx.x] = src[threadIdx.x];          // 128 threads * float4 = 512
}

// ---------------- zero initial hidden states ----------------
__global__ void init_kernel()
{
    int i = blockIdx.x * blockDim.x + threadIdx.x;
    if (i < BH) {
        g_h0[0][0][i] = 0.f; g_h0[1][0][i] = 0.f;
        g_h1[0][0][i] = 0.f; g_h1[1][0][i] = 0.f;
    }
}

__device__ __forceinline__ float fsig(float x)
{
    return 1.f / (1.f + __expf(-x));
}

// ---------------- shared tile buffers ----------------
struct SmemT {
    float As[64][65];   // A panel, transposed: As[kk][m], stride 65 (bank-friendly)
    float Ws[64][33];   // W panel: Ws[kk][c],  stride 33
};

// Accumulate  acc[r][c] += sum_k A[m][k] * W[col][k]  over k in [0, nk)
// A: row stride HH.  W: row stride IND, k offset wk0.  Double-buffered via
// register prefetch: next chunk's global loads are issued before the current
// chunk's 64-kk FMA loop, hiding L2 latency behind compute.
__device__ __forceinline__ void gemm_part(
    const float* __restrict__ A,
    const float* __restrict__ W, int wk0,
    int c0, int nk,
    float (&acc)[4][4], SmemT* sm)
{
    const int tid = threadIdx.x;
    const int tr4 = (tid & 15) * 4;   // row base in C
    const int tc4 = (tid >> 4) * 4;   // col base in C

    // fixed per-thread staging coordinates
    const int mA  = ((0*128 + tid) >> 4);     // computed per i below; kept simple
    (void)mA;

    float4 ra[8], rw[4];
    // ---- prefetch chunk 0 ----
    #pragma unroll
    for (int i = 0; i < 8; ++i) {
        int Q = i * 128 + tid, m = Q >> 4, qk = Q & 15;
        ra[i] = *(const float4*)(A + (size_t)m * HH + qk * 4);
    }
    #pragma unroll
    for (int i = 0; i < 4; ++i) {
        int Q = i * 128 + tid, c = Q >> 4, qk = Q & 15;
        rw[i] = *(const float4*)(W + (size_t)(c0 + c) * IND + wk0 + qk * 4);
    }

    for (int k0 = 0; k0 < nk; k0 += 64) {
        __syncthreads();
        // ---- store prefetched chunk into smem (A transposed) ----
        #pragma unroll
        for (int i = 0; i < 8; ++i) {
            int Q = i * 128 + tid, m = Q >> 4, qk = Q & 15;
            sm->As[qk*4+0][m] = ra[i].x;
            sm->As[qk*4+1][m] = ra[i].y;
            sm->As[qk*4+2][m] = ra[i].z;
            sm->As[qk*4+3][m] = ra[i].w;
        }
        #pragma unroll
        for (int i = 0; i < 4; ++i) {
            int Q = i * 128 + tid, c = Q >> 4, qk = Q & 15;
            sm->Ws[qk*4+0][c] = rw[i].x;
            sm->Ws[qk*4+1][c] = rw[i].y;
            sm->Ws[qk*4+2][c] = rw[i].z;
            sm->Ws[qk*4+3][c] = rw[i].w;
        }
        __syncthreads();
        // ---- issue next chunk's global loads (latency overlapped below) ----
        if (k0 + 64 < nk) {
            int k1 = k0 + 64;
            #pragma unroll
            for (int i = 0; i < 8; ++i) {
                int Q = i * 128 + tid, m = Q >> 4, qk = Q & 15;
                ra[i] = *(const float4*)(A + (size_t)m * HH + k1 + qk * 4);
            }
            #pragma unroll
            for (int i = 0; i < 4; ++i) {
                int Q = i * 128 + tid, c = Q >> 4, qk = Q & 15;
                rw[i] = *(const float4*)(W + (size_t)(c0 + c) * IND + wk0 + k1 + qk * 4);
            }
        }
        // ---- 4x4 register micro-tile over 64 kk ----
        #pragma unroll 16
        for (int kk = 0; kk < 64; ++kk) {
            float a0 = sm->As[kk][tr4+0];
            float a1 = sm->As[kk][tr4+1];
            float a2 = sm->As[kk][tr4+2];
            float a3 = sm->As[kk][tr4+3];
            float w0 = sm->Ws[kk][tc4+0];
            float w1 = sm->Ws[kk][tc4+1];
            float w2 = sm->Ws[kk][tc4+2];
            float w3 = sm->Ws[kk][tc4+3];
            acc[0][0] += a0*w0; acc[0][1] += a0*w1; acc[0][2] += a0*w2; acc[0][3] += a0*w3;
            acc[1][0] += a1*w0; acc[1][1] += a1*w1; acc[1][2] += a1*w2; acc[1][3] += a1*w3;
            acc[2][0] += a2*w0; acc[2][1] += a2*w1; acc[2][2] += a2*w2; acc[2][3] += a2*w3;
            acc[3][0] += a3*w0; acc[3][1] += a3*w1; acc[3][2] += a3*w2; acc[3][3] += a3*w3;
        }
    }
}

// ---------------- phase 1: r,z gates (both halves) + s-gate input half ----------------
// grid = 192 blocks x 128 threads
__global__ void __launch_bounds__(128)
rz_kernel(int t,
          const float* __restrict__ Wr, const float* __restrict__ Wz,
          const float* __restrict__ Wsv,
          const float* __restrict__ br, const float* __restrict__ bz,
          const float* __restrict__ bsv)
{
    __shared__ SmemT sm;
    int bid = blockIdx.x;
    int layer, d, gate, tile;
    if (bid < 128) {
        layer = (bid >> 6) & 1;
        d     = (bid >> 5) & 1;
        gate  = (bid >> 4) & 1;   // 0 = r, 1 = z
        tile  =  bid       & 15;
    } else {
        int s2 = bid - 128;
        layer = (s2 >> 5) & 1;
        d     = (s2 >> 4) & 1;
        gate  = 2;                // s-gate input half
        tile  =  s2       & 15;
    }
    if (layer == 0 && t >= SQ) return;   // layer0 active for t = 0..255
    if (layer == 1 && t <  1 ) return;   // layer1 works on u = t-1

    const float* Ain;
    const float* Ah;
    if (layer == 0) {
        int rt = d ? (SQ - 1 - t) : t;           // backward dir reads flipped input
        Ain = g_x + (size_t)rt * BH;
        Ah  = g_h0[d][t & 1];
    } else {
        int u = t - 1;
        Ain = g_y0[d] + (size_t)u * BH;
        Ah  = g_h1[d][u & 1];
    }

    const float* Wg = (gate == 0 ? Wr : (gate == 1 ? Wz : Wsv))
                      + (size_t)(d * 2 + layer) * HH * IND;
    const float* bvec = (gate == 0 ? br : (gate == 1 ? bz : bsv))
                      + (size_t)(d * 2 + layer) * HH;
    int c0 = tile * 32;

    float acc[4][4];
    #pragma unroll
    for (int r = 0; r < 4; ++r)
        #pragma unroll
        for (int c = 0; c < 4; ++c) acc[r][c] = 0.f;

    // input half (k = 0..511)
    gemm_part(Ain, Wg, 0,  c0, HH, acc, &sm);
    // recurrent half (k = 512..1023) only for r,z
    if (gate < 2)
        gemm_part(Ah,  Wg, HH, c0, HH, acc, &sm);

    int tr4 = (threadIdx.x & 15) * 4;
    int tc4 = (threadIdx.x >> 4) * 4;

    if (gate == 0) {            // r -> store r * h_prev
        #pragma unroll
        for (int r = 0; r < 4; ++r)
            #pragma unroll
            for (int c = 0; c < 4; ++c) {
                int m = tr4 + r, col = c0 + tc4 + c;
                float pre = acc[r][c] + bvec[col];
                g_rh[layer][d][m * HH + col] = fsig(pre) * Ah[m * HH + col];
            }
    } else if (gate == 1) {     // z
        #pragma unroll
        for (int r = 0; r < 4; ++r)
            #pragma unroll
            for (int c = 0; c < 4; ++c) {
                int m = tr4 + r, col = c0 + tc4 + c;
                g_z[layer][d][m * HH + col] = fsig(acc[r][c] + bvec[col]);
            }
    } else {                    // s input-half partial (+ bias)
        #pragma unroll
        for (int r = 0; r < 4; ++r)
            #pragma unroll
            for (int c = 0; c < 4; ++c) {
                int m = tr4 + r, col = c0 + tc4 + c;
                g_ps[layer][d][m * HH + col] = acc[r][c] + bvec[col];
            }
    }
}

// ---------------- phase 2a: s recurrent-half GEMM, K split over 2 blocks ----------------
// grid = 128 blocks x 128 threads:
//   layer=(bid>>6)&1, dir=(bid>>5)&1, khalf=(bid>>4)&1, tile=bid&15
// Each block computes a 64x32 partial over K range [khalf*256, khalf*256+256)
// of the recurrent half, writing to g_sp.
__global__ void __launch_bounds__(128)
s1_kernel(int t, const float* __restrict__ Wsv)
{
    __shared__ SmemT sm;
    int bid   = blockIdx.x;
    int layer = (bid >> 6) & 1;
    int d     = (bid >> 5) & 1;
    int kh    = (bid >> 4) & 1;
    int tile  =  bid       & 15;
    if (layer == 0 && t >= SQ) return;
    if (layer == 1 && t <  1 ) return;

    const float* Arh = g_rh[layer][d] + kh * 256;        // k-offset within rh
    const float* Wg  = Wsv + (size_t)(d * 2 + layer) * HH * IND;
    int c0 = tile * 32;

    float acc[4][4];
    #pragma unroll
    for (int r = 0; r < 4; ++r)
        #pragma unroll
        for (int c = 0; c < 4; ++c) acc[r][c] = 0.f;

    // recurrent half of s-gate: W columns 512..1023, this block's K quarter
    gemm_part(Arh, Wg, HH + kh * 256, c0, 256, acc, &sm);

    int tr4 = (threadIdx.x & 15) * 4;
    int tc4 = (threadIdx.x >> 4) * 4;
    float* dst = g_sp[layer][d][kh];
    #pragma unroll
    for (int r = 0; r < 4; ++r)
        #pragma unroll
        for (int c = 0; c < 4; ++c) {
            int m = tr4 + r, col = c0 + tc4 + c;
            dst[m * HH + col] = acc[r][c];
        }
}

// ---------------- phase 2b: combine + tanh + gate mix + h update ----------------
// grid = 512 blocks x 256 threads; elementwise over [layer][dir][BH]
__global__ void __launch_bounds__(256)
s2_kernel(int t, float* __restrict__ dout)
{
    int bid   = blockIdx.x;              // 0..511
    int cell  = bid >> 7;                // 0..3 -> (layer, dir)
    int layer = (cell >> 1) & 1;
    int d     =  cell       & 1;
    if (layer == 0 && t >= SQ) return;
    if (layer == 1 && t <  1 ) return;

    int u   = (layer == 0) ? t : (t - 1);
    int idx = (bid & 127) * 256 + threadIdx.x;   // 0..BH-1
    int m   = idx >> 9;                          // batch row
    int col = idx & 511;                         // hidden col

    float pre = g_ps[layer][d][idx] + g_sp[layer][d][0][idx] + g_sp[layer][d][1][idx];
    float s   = tanhf(pre);
    float z   = g_z[layer][d][idx];

    const float* hp = (layer == 0) ? g_h0[d][u & 1]       : g_h1[d][u & 1];
    float*       hn = (layer == 0) ? g_h0[d][(u + 1) & 1] : g_h1[d][(u + 1) & 1];

    float h = z * hp[idx] + (1.f - z) * s;
    hn[idx] = h;

    if (layer == 0) {
        g_y0[d][(size_t)u * BH + idx] = h;
        if (u == SQ - 1)
            dout[OUT_SZ + (size_t)(d * 2 + 0) * BH + idx] = h;
    } else {
        dout[(size_t)u * BB * (2 * HH) + (size_t)m * (2 * HH) + d * HH + col] = h;
        if (u == SQ - 1)
            dout[OUT_SZ + (size_t)(d * 2 + 1) * BH + idx] = h;
    }
}

// ---------------- launcher (graph-capturable: kernels only) ----------------
extern "C" void kernel_launch(void* const* d_in, const int* in_sizes, int n_in,
                              void* d_out, int out_size)
{
    const int*   tok = (const int*)  d_in[0];
    const float* emb = (const float*)d_in[1];
    const float* Wr  = (const float*)d_in[2];
    const float* Wz  = (const float*)d_in[3];
    const float* Wsv = (const float*)d_in[4];
    const float* br  = (const float*)d_in[5];
    const float* bz  = (const float*)d_in[6];
    const float* bsv = (const float*)d_in[7];
    float* outp = (float*)d_out;

    embed_kernel<<<SQ * BB, 128>>>(tok, emb);
    init_kernel<<<(BH + 255) / 256, 256>>>();

    // global step t: layer0 computes time t (t<256), layer1 computes time t-1 (t>=1)
    for (int t = 0; t <= SQ; ++t) {
        rz_kernel<<<192, 128>>>(t, Wr, Wz, Wsv, br, bz, bsv);
        s1_kernel<<<128, 128>>>(t, Wsv);
        s2_kernel<<<512, 256>>>(t, outp);
    }
}

// round 12
// speedup vs baseline: 1.5182x; 1.0121x over previous
#include <cuda_runtime.h>
#include <math.h>

// Problem constants
#define SQ   256
#define BB   64
#define HH   512
#define IND  1024
#define BH   (BB*HH)      // 32768
#define SBH  (SQ*BB*HH)   // 8388608
#define OUT_SZ ((size_t)SQ*BB*2*HH)

// ---------------- device scratch ----------------
__device__ float g_x  [SBH];            // embedded input [s][b][f]
__device__ float g_y0 [2][SBH];         // layer-0 output per dir
__device__ float g_h0 [2][2][BH];       // layer-0 hidden ping-pong [dir][parity]
__device__ float g_h1 [2][2][BH];       // layer-1 hidden ping-pong
__device__ float g_pin[2][3][SBH];      // precomputed L0 input-half preact [d][gate r/z/s]
__device__ float g_paL0[2][2][2][BH];   // L0 r/z recurrent partials [d][gate][slice]
__device__ float g_paL1[2][2][4][BH];   // L1 r/z partials [d][gate][slice]
__device__ float g_psp [2][2][BH];      // L1 s-input partials [d][slice]
__device__ float g_sp  [2][2][4][BH];   // s recurrent partials [layer][d][slice]

__device__ __forceinline__ float fsig(float x) { return 1.f / (1.f + __expf(-x)); }

// ---------------- embedding gather ----------------
__global__ void embed_kernel(const int* __restrict__ tok,
                             const float* __restrict__ emb)
{
    int row = blockIdx.x;
    int t = tok[row];
    const float4* src = (const float4*)(emb + (size_t)t * HH);
    float4* dst = (float4*)(g_x + (size_t)row * HH);
    dst[threadIdx.x] = src[threadIdx.x];
}

__global__ void init_kernel()
{
    int i = blockIdx.x * blockDim.x + threadIdx.x;
    if (i < BH) {
        g_h0[0][0][i] = 0.f; g_h0[1][0][i] = 0.f;
        g_h1[0][0][i] = 0.f; g_h1[1][0][i] = 0.f;
    }
}

// ---------------- shared tile buffers ----------------
struct SmemT {
    float As[64][65];   // A panel, transposed: As[kk][m]
    float Ws[64][33];   // W panel: Ws[kk][c]
};

// acc[r][c] += sum_k A[m][k]*W[col][k], k in [0,nk). A row stride HH,
// W row stride IND with k offset wk0. Register-prefetch double buffering.
__device__ __forceinline__ void gemm_part(
    const float* __restrict__ A,
    const float* __restrict__ W, int wk0,
    int c0, int nk,
    float (&acc)[4][4], SmemT* sm)
{
    const int tid = threadIdx.x;
    const int tr4 = (tid & 15) * 4;
    const int tc4 = (tid >> 4) * 4;

    float4 ra[8], rw[4];
    #pragma unroll
    for (int i = 0; i < 8; ++i) {
        int Q = i * 128 + tid, m = Q >> 4, qk = Q & 15;
        ra[i] = *(const float4*)(A + (size_t)m * HH + qk * 4);
    }
    #pragma unroll
    for (int i = 0; i < 4; ++i) {
        int Q = i * 128 + tid, c = Q >> 4, qk = Q & 15;
        rw[i] = *(const float4*)(W + (size_t)(c0 + c) * IND + wk0 + qk * 4);
    }

    for (int k0 = 0; k0 < nk; k0 += 64) {
        __syncthreads();
        #pragma unroll
        for (int i = 0; i < 8; ++i) {
            int Q = i * 128 + tid, m = Q >> 4, qk = Q & 15;
            sm->As[qk*4+0][m] = ra[i].x;
            sm->As[qk*4+1][m] = ra[i].y;
            sm->As[qk*4+2][m] = ra[i].z;
            sm->As[qk*4+3][m] = ra[i].w;
        }
        #pragma unroll
        for (int i = 0; i < 4; ++i) {
            int Q = i * 128 + tid, c = Q >> 4, qk = Q & 15;
            sm->Ws[qk*4+0][c] = rw[i].x;
            sm->Ws[qk*4+1][c] = rw[i].y;
            sm->Ws[qk*4+2][c] = rw[i].z;
            sm->Ws[qk*4+3][c] = rw[i].w;
        }
        __syncthreads();
        if (k0 + 64 < nk) {
            int k1 = k0 + 64;
            #pragma unroll
            for (int i = 0; i < 8; ++i) {
                int Q = i * 128 + tid, m = Q >> 4, qk = Q & 15;
                ra[i] = *(const float4*)(A + (size_t)m * HH + k1 + qk * 4);
            }
            #pragma unroll
            for (int i = 0; i < 4; ++i) {
                int Q = i * 128 + tid, c = Q >> 4, qk = Q & 15;
                rw[i] = *(const float4*)(W + (size_t)(c0 + c) * IND + wk0 + k1 + qk * 4);
            }
        }
        #pragma unroll 16
        for (int kk = 0; kk < 64; ++kk) {
            float a0 = sm->As[kk][tr4+0];
            float a1 = sm->As[kk][tr4+1];
            float a2 = sm->As[kk][tr4+2];
            float a3 = sm->As[kk][tr4+3];
            float w0 = sm->Ws[kk][tc4+0];
            float w1 = sm->Ws[kk][tc4+1];
            float w2 = sm->Ws[kk][tc4+2];
            float w3 = sm->Ws[kk][tc4+3];
            acc[0][0] += a0*w0; acc[0][1] += a0*w1; acc[0][2] += a0*w2; acc[0][3] += a0*w3;
            acc[1][0] += a1*w0; acc[1][1] += a1*w1; acc[1][2] += a1*w2; acc[1][3] += a1*w3;
            acc[2][0] += a2*w0; acc[2][1] += a2*w1; acc[2][2] += a2*w2; acc[2][3] += a2*w3;
            acc[3][0] += a3*w0; acc[3][1] += a3*w1; acc[3][2] += a3*w2; acc[3][3] += a3*w3;
        }
    }
}

__device__ __forceinline__ void store_acc(float* dst, int c0, float (&acc)[4][4])
{
    int tr4 = (threadIdx.x & 15) * 4;
    int tc4 = (threadIdx.x >> 4) * 4;
    #pragma unroll
    for (int r = 0; r < 4; ++r)
        #pragma unroll
        for (int c = 0; c < 4; ++c)
            dst[(tr4 + r) * HH + c0 + tc4 + c] = acc[r][c];
}

// ---------------- one-time: L0 input-half preactivations for all timesteps ----------------
__global__ void __launch_bounds__(128)
pre_kernel(const float* __restrict__ Wr, const float* __restrict__ Wz,
           const float* __restrict__ Wsv)
{
    __shared__ SmemT sm;
    int bid  = blockIdx.x;
    int job  = bid >> 12;            // 0..5
    int d    = job / 3;
    int gate = job % 3;
    int rem  = bid & 4095;
    int rowt = rem >> 4;             // 0..255
    int tile = rem & 15;

    const float* A = g_x + (size_t)rowt * 64 * HH;
    const float* Wsel = (gate == 0) ? Wr : (gate == 1) ? Wz : Wsv;
    const float* W = Wsel + (size_t)(d * 2 + 0) * HH * IND;   // layer 0, input half

    float acc[4][4];
    #pragma unroll
    for (int r = 0; r < 4; ++r)
        #pragma unroll
        for (int c = 0; c < 4; ++c) acc[r][c] = 0.f;

    gemm_part(A, W, 0, tile * 32, HH, acc, &sm);
    store_acc(g_pin[d][gate] + (size_t)rowt * 64 * HH, tile * 32, acc);
}

// ---------------- phase A: all r/z GEMM slices + L1 s-input slices ----------------
// grid = 448 x 128 threads; all jobs K=256
__global__ void __launch_bounds__(128)
gemmA_kernel(int t,
             const float* __restrict__ Wr, const float* __restrict__ Wz,
             const float* __restrict__ Wsv)
{
    __shared__ SmemT sm;
    int bid = blockIdx.x;
    const float* A; const float* W; float* dst;
    int wk0, tile;

    if (bid < 128) {                        // L0 r/z recurrent, K=512 in 2 slices
        if (t >= SQ) return;
        int d     = (bid >> 6) & 1;
        int gate  = (bid >> 5) & 1;
        int slice = (bid >> 4) & 1;
        tile      =  bid       & 15;
        A   = g_h0[d][t & 1] + slice * 256;
        W   = (gate ? Wz : Wr) + (size_t)(d * 2 + 0) * HH * IND;
        wk0 = HH + slice * 256;
        dst = g_paL0[d][gate][slice];
    } else if (bid < 384) {                 // L1 r/z, K=1024 in 4 slices
        if (t < 1) return;
        int q     = bid - 128;
        int d     = (q >> 7) & 1;
        int gate  = (q >> 6) & 1;
        int slice = (q >> 4) & 3;
        tile      =  q       & 15;
        int u = t - 1;
        if (slice < 2) A = g_y0[d] + (size_t)u * BH + slice * 256;
        else           A = g_h1[d][u & 1] + (slice - 2) * 256;
        W   = (gate ? Wz : Wr) + (size_t)(d * 2 + 1) * HH * IND;
        wk0 = slice * 256;
        dst = g_paL1[d][gate][slice];
    } else {                                // L1 s-input, K=512 in 2 slices
        if (t < 1) return;
        int q     = bid - 384;
        int d     = (q >> 5) & 1;
        int slice = (q >> 4) & 1;
        tile      =  q       & 15;
        int u = t - 1;
        A   = g_y0[d] + (size_t)u * BH + slice * 256;
        W   = Wsv + (size_t)(d * 2 + 1) * HH * IND;
        wk0 = slice * 256;
        dst = g_psp[d][slice];
    }

    float acc[4][4];
    #pragma unroll
    for (int r = 0; r < 4; ++r)
        #pragma unroll
        for (int c = 0; c < 4; ++c) acc[r][c] = 0.f;

    gemm_part(A, W, wk0, tile * 32, 256, acc, &sm);
    store_acc(dst, tile * 32, acc);
}

// ---------------- phase S: fused (r-gate + r*h) -> s recurrent GEMM ----------------
// grid = 256 x 128: layer=(bid>>7)&1, d=(bid>>6)&1, slice=(bid>>4)&3, tile=bid&15
// Each block builds its 64x128 r*h tile in smem (transposed) from the gemmA
// partials, then GEMMs it against Wsv's recurrent columns [slice k-range].
struct SmemS {
    float As[128][65];
    float Ws[64][33];
};

__global__ void __launch_bounds__(128)
gemmS_kernel(int t, const float* __restrict__ Wsv, const float* __restrict__ br)
{
    __shared__ SmemS sm;
    int bid   = blockIdx.x;
    int layer = (bid >> 7) & 1;
    int d     = (bid >> 6) & 1;
    int slice = (bid >> 4) & 3;
    int tile  =  bid       & 15;
    if (layer == 0 && t >= SQ) return;
    if (layer == 1 && t <  1 ) return;

    const int tid = threadIdx.x;
    int u = (layer == 0) ? t : (t - 1);
    const float* h = (layer == 0) ? g_h0[d][u & 1] : g_h1[d][u & 1];
    int boffbase = (d * 2 + layer) * HH;

    // ---- phase 1: compute r*h 64x128 tile into As (transposed) ----
    int rt = d ? (SQ - 1 - t) : t;   // only used for layer 0
    #pragma unroll
    for (int i = 0; i < 16; ++i) {
        int q  = i * 128 + tid;      // 0..2047 float4 jobs
        int m  = q >> 5;             // 0..63
        int kq = q & 31;             // 0..31
        int col = slice * 128 + kq * 4;
        int idx = m * HH + col;
        float4 rp;
        if (layer == 0) {
            float4 a = *(const float4*)(g_pin[d][0] + (size_t)rt * BH + idx);
            float4 b = *(const float4*)(g_paL0[d][0][0] + idx);
            float4 c = *(const float4*)(g_paL0[d][0][1] + idx);
            rp.x = a.x + b.x + c.x; rp.y = a.y + b.y + c.y;
            rp.z = a.z + b.z + c.z; rp.w = a.w + b.w + c.w;
        } else {
            float4 a = *(const float4*)(g_paL1[d][0][0] + idx);
            float4 b = *(const float4*)(g_paL1[d][0][1] + idx);
            float4 c = *(const float4*)(g_paL1[d][0][2] + idx);
            float4 e = *(const float4*)(g_paL1[d][0][3] + idx);
            rp.x = a.x + b.x + c.x + e.x; rp.y = a.y + b.y + c.y + e.y;
            rp.z = a.z + b.z + c.z + e.z; rp.w = a.w + b.w + c.w + e.w;
        }
        float4 bb = *(const float4*)(br + boffbase + col);
        float4 hv = *(const float4*)(h + idx);
        sm.As[kq*4+0][m] = fsig(rp.x + bb.x) * hv.x;
        sm.As[kq*4+1][m] = fsig(rp.y + bb.y) * hv.y;
        sm.As[kq*4+2][m] = fsig(rp.z + bb.z) * hv.z;
        sm.As[kq*4+3][m] = fsig(rp.w + bb.w) * hv.w;
    }

    // ---- phase 2: GEMM, A from smem, W staged in 64-k chunks ----
    const float* W = Wsv + (size_t)(d * 2 + layer) * HH * IND;
    int wk0 = HH + slice * 128;
    int c0  = tile * 32;
    const int tr4 = (tid & 15) * 4;
    const int tc4 = (tid >> 4) * 4;

    float acc[4][4];
    #pragma unroll
    for (int r = 0; r < 4; ++r)
        #pragma unroll
        for (int c = 0; c < 4; ++c) acc[r][c] = 0.f;

    float4 rw[4];
    #pragma unroll
    for (int i = 0; i < 4; ++i) {
        int Q = i * 128 + tid, c = Q >> 4, qk = Q & 15;
        rw[i] = *(const float4*)(W + (size_t)(c0 + c) * IND + wk0 + qk * 4);
    }

    #pragma unroll
    for (int k0 = 0; k0 < 128; k0 += 64) {
        __syncthreads();   // As ready (first iter) / Ws free (second iter)
        #pragma unroll
        for (int i = 0; i < 4; ++i) {
            int Q = i * 128 + tid, c = Q >> 4, qk = Q & 15;
            sm.Ws[qk*4+0][c] = rw[i].x;
            sm.Ws[qk*4+1][c] = rw[i].y;
            sm.Ws[qk*4+2][c] = rw[i].z;
            sm.Ws[qk*4+3][c] = rw[i].w;
        }
        __syncthreads();
        if (k0 == 0) {
            #pragma unroll
            for (int i = 0; i < 4; ++i) {
                int Q = i * 128 + tid, c = Q >> 4, qk = Q & 15;
                rw[i] = *(const float4*)(W + (size_t)(c0 + c) * IND + wk0 + 64 + qk * 4);
            }
        }
        #pragma unroll 16
        for (int kk = 0; kk < 64; ++kk) {
            float a0 = sm.As[k0+kk][tr4+0];
            float a1 = sm.As[k0+kk][tr4+1];
            float a2 = sm.As[k0+kk][tr4+2];
            float a3 = sm.As[k0+kk][tr4+3];
            float w0 = sm.Ws[kk][tc4+0];
            float w1 = sm.Ws[kk][tc4+1];
            float w2 = sm.Ws[kk][tc4+2];
            float w3 = sm.Ws[kk][tc4+3];
            acc[0][0] += a0*w0; acc[0][1] += a0*w1; acc[0][2] += a0*w2; acc[0][3] += a0*w3;
            acc[1][0] += a1*w0; acc[1][1] += a1*w1; acc[1][2] += a1*w2; acc[1][3] += a1*w3;
            acc[2][0] += a2*w0; acc[2][1] += a2*w1; acc[2][2] += a2*w2; acc[2][3] += a2*w3;
            acc[3][0] += a3*w0; acc[3][1] += a3*w1; acc[3][2] += a3*w2; acc[3][3] += a3*w3;
        }
    }

    float* dst = g_sp[layer][d][slice];
    #pragma unroll
    for (int r = 0; r < 4; ++r)
        #pragma unroll
        for (int c = 0; c < 4; ++c)
            dst[(tr4 + r) * HH + c0 + tc4 + c] = acc[r][c];
}

// ---------------- combine S: z gate + tanh + gate mix + h update + outputs ----------------
// grid = 512 x 256
__global__ void __launch_bounds__(256)
combS_kernel(int t, const float* __restrict__ bz, const float* __restrict__ bsv,
             float* __restrict__ dout)
{
    int bid   = blockIdx.x;
    int cell  = bid >> 7;
    int layer = (cell >> 1) & 1;
    int d     =  cell       & 1;
    if (layer == 0 && t >= SQ) return;
    if (layer == 1 && t <  1 ) return;

    int u   = (layer == 0) ? t : (t - 1);
    int idx = (bid & 127) * 256 + threadIdx.x;
    int m   = idx >> 9;
    int col = idx & 511;
    int boff = (d * 2 + layer) * HH + col;

    // z gate from partials
    float zpre;
    float pre;
    if (layer == 0) {
        int rt = d ? (SQ - 1 - t) : t;
        zpre = g_pin[d][1][(size_t)rt * BH + idx]
             + g_paL0[d][1][0][idx] + g_paL0[d][1][1][idx];
        pre  = g_pin[d][2][(size_t)rt * BH + idx];
    } else {
        zpre = g_paL1[d][1][0][idx] + g_paL1[d][1][1][idx]
             + g_paL1[d][1][2][idx] + g_paL1[d][1][3][idx];
        pre  = g_psp[d][0][idx] + g_psp[d][1][idx];
    }
    float z = fsig(zpre + bz[boff]);

    pre += bsv[boff];
    pre += g_sp[layer][d][0][idx] + g_sp[layer][d][1][idx]
         + g_sp[layer][d][2][idx] + g_sp[layer][d][3][idx];
    float s = tanhf(pre);

    const float* hp = (layer == 0) ? g_h0[d][u & 1]       : g_h1[d][u & 1];
    float*       hn = (layer == 0) ? g_h0[d][(u + 1) & 1] : g_h1[d][(u + 1) & 1];

    float h = z * hp[idx] + (1.f - z) * s;
    hn[idx] = h;

    if (layer == 0) {
        g_y0[d][(size_t)u * BH + idx] = h;
        if (u == SQ - 1)
            dout[OUT_SZ + (size_t)(d * 2 + 0) * BH + idx] = h;
    } else {
        dout[(size_t)u * BB * (2 * HH) + (size_t)m * (2 * HH) + d * HH + col] = h;
        if (u == SQ - 1)
            dout[OUT_SZ + (size_t)(d * 2 + 1) * BH + idx] = h;
    }
}

// ---------------- launcher (774 graph nodes, under the ~1K aux-alloc threshold) ----------------
extern "C" void kernel_launch(void* const* d_in, const int* in_sizes, int n_in,
                              void* d_out, int out_size)
{
    const int*   tok = (const int*)  d_in[0];
    const float* emb = (const float*)d_in[1];
    const float* Wr  = (const float*)d_in[2];
    const float* Wz  = (const float*)d_in[3];
    const float* Wsv = (const float*)d_in[4];
    const float* br  = (const float*)d_in[5];
    const float* bz  = (const float*)d_in[6];
    const float* bsv = (const float*)d_in[7];
    float* outp = (float*)d_out;

    embed_kernel<<<SQ * BB, 128>>>(tok, emb);
    init_kernel<<<(BH + 255) / 256, 256>>>();
    pre_kernel<<<24576, 128>>>(Wr, Wz, Wsv);

    for (int t = 0; t <= SQ; ++t) {
        gemmA_kernel<<<448, 128>>>(t, Wr, Wz, Wsv);
        gemmS_kernel<<<256, 128>>>(t, Wsv, br);
        combS_kernel<<<512, 256>>>(t, bz, bsv, outp);
    }
}

// round 13
// speedup vs baseline: 1.5877x; 1.0458x over previous
#include <cuda_runtime.h>
#include <math.h>

// Problem constants
#define SQ   256
#define BB   64
#define HH   512
#define IND  1024
#define BH   (BB*HH)      // 32768
#define SBH  (SQ*BB*HH)   // 8388608
#define OUT_SZ ((size_t)SQ*BB*2*HH)
#define NBLK 448          // persistent grid size

// ---------------- device scratch ----------------
__device__ float g_x  [SBH];            // embedded input [s][b][f]
__device__ float g_y0 [2][SBH];         // layer-0 output per dir
__device__ float g_h0 [2][2][BH];       // layer-0 hidden ping-pong [dir][parity]
__device__ float g_h1 [2][2][BH];       // layer-1 hidden ping-pong
__device__ float g_rh [2][2][BH];       // r * h_prev [layer][dir]
__device__ float g_z  [2][2][BH];       // z gate
__device__ float g_pin[2][3][SBH];      // precomputed L0 input-half preact [d][gate]
__device__ float g_paL0[2][2][2][BH];   // L0 r/z recurrent partials [d][gate][slice]
__device__ float g_paL1[2][2][4][BH];   // L1 r/z partials [d][gate][slice]
__device__ float g_psp [2][2][BH];      // L1 s-input partials [d][slice]
__device__ float g_sp  [2][2][4][BH];   // s recurrent partials [layer][d][slice]
__device__ unsigned g_bar;              // grid barrier counter (reset by embed_kernel)

__device__ __forceinline__ float fsig(float x) { return 1.f / (1.f + __expf(-x)); }

// ---------------- grid-wide spin barrier ----------------
// Release: every thread fences (stores -> L2), block syncs, leader arrives.
// Acquire: leader polls counter via L2 atomics; post-spin gpu-scope fence
// emits CCTL.IVALL, invalidating this SM's L1 so later loads see fresh data.
__device__ __forceinline__ void grid_bar(unsigned target)
{
    __threadfence();
    __syncthreads();
    if (threadIdx.x == 0) {
        atomicAdd(&g_bar, 1u);
        while (atomicAdd(&g_bar, 0u) < target)
            __nanosleep(128);
        __threadfence();   // acquire + L1 invalidate
    }
    __syncthreads();
}

// ---------------- embedding gather (also resets barrier counter) ----------------
__global__ void embed_kernel(const int* __restrict__ tok,
                             const float* __restrict__ emb)
{
    if (blockIdx.x == 0 && threadIdx.x == 0) g_bar = 0u;
    int row = blockIdx.x;
    int t = tok[row];
    const float4* src = (const float4*)(emb + (size_t)t * HH);
    float4* dst = (float4*)(g_x + (size_t)row * HH);
    dst[threadIdx.x] = src[threadIdx.x];
}

__global__ void init_kernel()
{
    int i = blockIdx.x * blockDim.x + threadIdx.x;
    if (i < BH) {
        g_h0[0][0][i] = 0.f; g_h0[1][0][i] = 0.f;
        g_h1[0][0][i] = 0.f; g_h1[1][0][i] = 0.f;
    }
}

// ---------------- shared tile buffers ----------------
struct SmemT {
    float As[64][65];   // A panel, transposed: As[kk][m]
    float Ws[64][33];   // W panel: Ws[kk][c]
};

// acc[r][c] += sum_k A[m][k]*W[col][k], k in [0,nk). A row stride HH,
// W row stride IND with k offset wk0. Register-prefetch double buffering.
// A passed WITHOUT __restrict__ (mutable across phases); W is immutable.
__device__ __forceinline__ void gemm_part(
    const float* A,
    const float* __restrict__ W, int wk0,
    int c0, int nk,
    float (&acc)[4][4], SmemT* sm)
{
    const int tid = threadIdx.x;
    const int tr4 = (tid & 15) * 4;
    const int tc4 = (tid >> 4) * 4;

    float4 ra[8], rw[4];
    #pragma unroll
    for (int i = 0; i < 8; ++i) {
        int Q = i * 128 + tid, m = Q >> 4, qk = Q & 15;
        ra[i] = *(const float4*)(A + (size_t)m * HH + qk * 4);
    }
    #pragma unroll
    for (int i = 0; i < 4; ++i) {
        int Q = i * 128 + tid, c = Q >> 4, qk = Q & 15;
        rw[i] = *(const float4*)(W + (size_t)(c0 + c) * IND + wk0 + qk * 4);
    }

    for (int k0 = 0; k0 < nk; k0 += 64) {
        __syncthreads();
        #pragma unroll
        for (int i = 0; i < 8; ++i) {
            int Q = i * 128 + tid, m = Q >> 4, qk = Q & 15;
            sm->As[qk*4+0][m] = ra[i].x;
            sm->As[qk*4+1][m] = ra[i].y;
            sm->As[qk*4+2][m] = ra[i].z;
            sm->As[qk*4+3][m] = ra[i].w;
        }
        #pragma unroll
        for (int i = 0; i < 4; ++i) {
            int Q = i * 128 + tid, c = Q >> 4, qk = Q & 15;
            sm->Ws[qk*4+0][c] = rw[i].x;
            sm->Ws[qk*4+1][c] = rw[i].y;
            sm->Ws[qk*4+2][c] = rw[i].z;
            sm->Ws[qk*4+3][c] = rw[i].w;
        }
        __syncthreads();
        if (k0 + 64 < nk) {
            int k1 = k0 + 64;
            #pragma unroll
            for (int i = 0; i < 8; ++i) {
                int Q = i * 128 + tid, m = Q >> 4, qk = Q & 15;
                ra[i] = *(const float4*)(A + (size_t)m * HH + k1 + qk * 4);
            }
            #pragma unroll
            for (int i = 0; i < 4; ++i) {
                int Q = i * 128 + tid, c = Q >> 4, qk = Q & 15;
                rw[i] = *(const float4*)(W + (size_t)(c0 + c) * IND + wk0 + k1 + qk * 4);
            }
        }
        #pragma unroll 16
        for (int kk = 0; kk < 64; ++kk) {
            float a0 = sm->As[kk][tr4+0];
            float a1 = sm->As[kk][tr4+1];
            float a2 = sm->As[kk][tr4+2];
            float a3 = sm->As[kk][tr4+3];
            float w0 = sm->Ws[kk][tc4+0];
            float w1 = sm->Ws[kk][tc4+1];
            float w2 = sm->Ws[kk][tc4+2];
            float w3 = sm->Ws[kk][tc4+3];
            acc[0][0] += a0*w0; acc[0][1] += a0*w1; acc[0][2] += a0*w2; acc[0][3] += a0*w3;
            acc[1][0] += a1*w0; acc[1][1] += a1*w1; acc[1][2] += a1*w2; acc[1][3] += a1*w3;
            acc[2][0] += a2*w0; acc[2][1] += a2*w1; acc[2][2] += a2*w2; acc[2][3] += a2*w3;
            acc[3][0] += a3*w0; acc[3][1] += a3*w1; acc[3][2] += a3*w2; acc[3][3] += a3*w3;
        }
    }
}

__device__ __forceinline__ void store_acc(float* dst, int c0, float (&acc)[4][4])
{
    int tr4 = (threadIdx.x & 15) * 4;
    int tc4 = (threadIdx.x >> 4) * 4;
    #pragma unroll
    for (int r = 0; r < 4; ++r)
        #pragma unroll
        for (int c = 0; c < 4; ++c)
            dst[(tr4 + r) * HH + c0 + tc4 + c] = acc[r][c];
}

// ---------------- one-time: L0 input-half preactivations for all timesteps ----------------
__global__ void __launch_bounds__(128)
pre_kernel(const float* __restrict__ Wr, const float* __restrict__ Wz,
           const float* __restrict__ Wsv)
{
    __shared__ SmemT sm;
    int bid  = blockIdx.x;
    int job  = bid >> 12;            // 0..5
    int d    = job / 3;
    int gate = job % 3;
    int rem  = bid & 4095;
    int rowt = rem >> 4;             // 0..255
    int tile = rem & 15;

    const float* A = g_x + (size_t)rowt * 64 * HH;
    const float* Wsel = (gate == 0) ? Wr : (gate == 1) ? Wz : Wsv;
    const float* W = Wsel + (size_t)(d * 2 + 0) * HH * IND;

    float acc[4][4];
    #pragma unroll
    for (int r = 0; r < 4; ++r)
        #pragma unroll
        for (int c = 0; c < 4; ++c) acc[r][c] = 0.f;

    gemm_part(A, W, 0, tile * 32, HH, acc, &sm);
    store_acc(g_pin[d][gate] + (size_t)rowt * 64 * HH, tile * 32, acc);
}

// ---------------- the persistent recurrence kernel ----------------
// 448 blocks x 128 threads, 4 CTAs/SM guaranteed resident
// (regs capped 128, smem 25088 B/block -> 100 KB/SM, capacity 528 >= 448).
__global__ void __launch_bounds__(128, 4)
persist_kernel(const float* __restrict__ Wr, const float* __restrict__ Wz,
               const float* __restrict__ Wsv,
               const float* __restrict__ br, const float* __restrict__ bz,
               const float* __restrict__ bsv,
               float* __restrict__ dout)
{
    __shared__ SmemT sm;
    const int bid = blockIdx.x;
    const int tid = threadIdx.x;
    const int gtid = bid * 128 + tid;
    unsigned tgt = 0;

    for (int t = 0; t <= SQ; ++t) {
        // ================= P1: gemmA (r/z all slices + L1 s-input) =================
        {
            const float* A = 0; const float* W = 0; float* dst = 0;
            int wk0 = 0, tile = 0, active = 0;
            if (bid < 128) {                        // L0 r/z recurrent, K=512 in 2 slices
                if (t < SQ) {
                    int d     = (bid >> 6) & 1;
                    int gate  = (bid >> 5) & 1;
                    int slice = (bid >> 4) & 1;
                    tile      =  bid       & 15;
                    A   = g_h0[d][t & 1] + slice * 256;
                    W   = (gate ? Wz : Wr) + (size_t)(d * 2 + 0) * HH * IND;
                    wk0 = HH + slice * 256;
                    dst = g_paL0[d][gate][slice];
                    active = 1;
                }
            } else if (bid < 384) {                 // L1 r/z, K=1024 in 4 slices
                if (t >= 1) {
                    int q     = bid - 128;
                    int d     = (q >> 7) & 1;
                    int gate  = (q >> 6) & 1;
                    int slice = (q >> 4) & 3;
                    tile      =  q       & 15;
                    int u = t - 1;
                    if (slice < 2) A = g_y0[d] + (size_t)u * BH + slice * 256;
                    else           A = g_h1[d][u & 1] + (slice - 2) * 256;
                    W   = (gate ? Wz : Wr) + (size_t)(d * 2 + 1) * HH * IND;
                    wk0 = slice * 256;
                    dst = g_paL1[d][gate][slice];
                    active = 1;
                }
            } else {                                // L1 s-input, K=512 in 2 slices
                if (t >= 1) {
                    int q     = bid - 384;
                    int d     = (q >> 5) & 1;
                    int slice = (q >> 4) & 1;
                    tile      =  q       & 15;
                    int u = t - 1;
                    A   = g_y0[d] + (size_t)u * BH + slice * 256;
                    W   = Wsv + (size_t)(d * 2 + 1) * HH * IND;
                    wk0 = slice * 256;
                    dst = g_psp[d][slice];
                    active = 1;
                }
            }
            if (active) {
                float acc[4][4];
                #pragma unroll
                for (int r = 0; r < 4; ++r)
                    #pragma unroll
                    for (int c = 0; c < 4; ++c) acc[r][c] = 0.f;
                gemm_part(A, W, wk0, tile * 32, 256, acc, &sm);
                store_acc(dst, tile * 32, acc);
            }
        }
        tgt += NBLK; grid_bar(tgt);

        // ================= P2: combA (r sigmoid + r*h, z sigmoid) =================
        for (int e = gtid; e < 4 * BH; e += NBLK * 128) {
            int cell  = e >> 15;
            int layer = cell >> 1;
            int d     = cell & 1;
            if (layer == 0 && t >= SQ) continue;
            if (layer == 1 && t <  1 ) continue;
            int u   = (layer == 0) ? t : (t - 1);
            int idx = e & (BH - 1);
            int col = idx & 511;

            const float* h = (layer == 0) ? g_h0[d][u & 1] : g_h1[d][u & 1];
            float rpre, zpre;
            if (layer == 0) {
                int rt = d ? (SQ - 1 - t) : t;
                rpre = g_pin[d][0][(size_t)rt * BH + idx]
                     + g_paL0[d][0][0][idx] + g_paL0[d][0][1][idx];
                zpre = g_pin[d][1][(size_t)rt * BH + idx]
                     + g_paL0[d][1][0][idx] + g_paL0[d][1][1][idx];
            } else {
                rpre = g_paL1[d][0][0][idx] + g_paL1[d][0][1][idx]
                     + g_paL1[d][0][2][idx] + g_paL1[d][0][3][idx];
                zpre = g_paL1[d][1][0][idx] + g_paL1[d][1][1][idx]
                     + g_paL1[d][1][2][idx] + g_paL1[d][1][3][idx];
            }
            int boff = (d * 2 + layer) * HH + col;
            g_rh[layer][d][idx] = fsig(rpre + br[boff]) * h[idx];
            g_z [layer][d][idx] = fsig(zpre + bz[boff]);
        }
        tgt += NBLK; grid_bar(tgt);

        // ================= P3: gemmS (s recurrent, K=512 in 4 slices) =================
        if (bid < 256) {
            int layer = (bid >> 7) & 1;
            int d     = (bid >> 6) & 1;
            int slice = (bid >> 4) & 3;
            int tile  =  bid       & 15;
            int active = !((layer == 0 && t >= SQ) || (layer == 1 && t < 1));
            if (active) {
                const float* A = g_rh[layer][d] + slice * 128;
                const float* W = Wsv + (size_t)(d * 2 + layer) * HH * IND;
                float acc[4][4];
                #pragma unroll
                for (int r = 0; r < 4; ++r)
                    #pragma unroll
                    for (int c = 0; c < 4; ++c) acc[r][c] = 0.f;
                gemm_part(A, W, HH + slice * 128, tile * 32, 128, acc, &sm);
                store_acc(g_sp[layer][d][slice], tile * 32, acc);
            }
        }
        tgt += NBLK; grid_bar(tgt);

        // ================= P4: combS (tanh + gate mix + h update + outputs) =================
        for (int e = gtid; e < 4 * BH; e += NBLK * 128) {
            int cell  = e >> 15;
            int layer = cell >> 1;
            int d     = cell & 1;
            if (layer == 0 && t >= SQ) continue;
            if (layer == 1 && t <  1 ) continue;
            int u   = (layer == 0) ? t : (t - 1);
            int idx = e & (BH - 1);
            int m   = idx >> 9;
            int col = idx & 511;

            float pre;
            if (layer == 0) {
                int rt = d ? (SQ - 1 - t) : t;
                pre = g_pin[d][2][(size_t)rt * BH + idx];
            } else {
                pre = g_psp[d][0][idx] + g_psp[d][1][idx];
            }
            pre += bsv[(d * 2 + layer) * HH + col];
            pre += g_sp[layer][d][0][idx] + g_sp[layer][d][1][idx]
                 + g_sp[layer][d][2][idx] + g_sp[layer][d][3][idx];

            float s = tanhf(pre);
            float z = g_z[layer][d][idx];

            const float* hp = (layer == 0) ? g_h0[d][u & 1]       : g_h1[d][u & 1];
            float*       hn = (layer == 0) ? g_h0[d][(u + 1) & 1] : g_h1[d][(u + 1) & 1];

            float h = z * hp[idx] + (1.f - z) * s;
            hn[idx] = h;

            if (layer == 0) {
                g_y0[d][(size_t)u * BH + idx] = h;
                if (u == SQ - 1)
                    dout[OUT_SZ + (size_t)(d * 2 + 0) * BH + idx] = h;
            } else {
                dout[(size_t)u * BB * (2 * HH) + (size_t)m * (2 * HH) + d * HH + col] = h;
                if (u == SQ - 1)
                    dout[OUT_SZ + (size_t)(d * 2 + 1) * BH + idx] = h;
            }
        }
        tgt += NBLK; grid_bar(tgt);
    }
}

// ---------------- launcher: 4 graph nodes ----------------
extern "C" void kernel_launch(void* const* d_in, const int* in_sizes, int n_in,
                              void* d_out, int out_size)
{
    const int*   tok = (const int*)  d_in[0];
    const float* emb = (const float*)d_in[1];
    const float* Wr  = (const float*)d_in[2];
    const float* Wz  = (const float*)d_in[3];
    const float* Wsv = (const float*)d_in[4];
    const float* br  = (const float*)d_in[5];
    const float* bz  = (const float*)d_in[6];
    const float* bsv = (const float*)d_in[7];
    float* outp = (float*)d_out;

    embed_kernel<<<SQ * BB, 128>>>(tok, emb);
    init_kernel<<<(BH + 255) / 256, 256>>>();
    pre_kernel<<<24576, 128>>>(Wr, Wz, Wsv);
    persist_kernel<<<NBLK, 128>>>(Wr, Wz, Wsv, br, bz, bsv, outp);
}

// round 14
// speedup vs baseline: 3.0834x; 1.9420x over previous
#include <cuda_runtime.h>
#include <cuda_bf16.h>
#include <math.h>

// Problem constants
#define SQ   256
#define BB   64
#define HH   512
#define IND  1024
#define BH   (BB*HH)      // 32768
#define SBH  (SQ*BB*HH)   // 8388608
#define OUT_SZ ((size_t)SQ*BB*2*HH)
#define NBLK 448          // persistent grid size
#define LDA  72           // bf16 elements per smem row (144 B, 16B-aligned, ldmatrix conflict-free)

// ---------------- fp32 scratch ----------------
__device__ float g_h0 [2][2][BH];       // layer-0 hidden ping-pong [dir][parity]
__device__ float g_h1 [2][2][BH];       // layer-1 hidden ping-pong
__device__ float g_z  [2][2][BH];       // z gate
__device__ float g_pin[2][3][SBH];      // precomputed L0 input-half preact [d][gate]
__device__ float g_paL0[2][2][2][BH];   // L0 r/z recurrent partials [d][gate][slice]
__device__ float g_paL1[2][2][4][BH];   // L1 r/z partials [d][gate][slice]
__device__ float g_psp [2][2][BH];      // L1 s-input partials [d][slice]
__device__ float g_sp  [2][2][4][BH];   // s recurrent partials [layer][d][slice]
__device__ unsigned g_bar;              // grid barrier counter

// ---------------- bf16 split operands (hi + lo) ----------------
__device__ __align__(16) __nv_bfloat16 g_xh [SBH],        g_xl [SBH];
__device__ __align__(16) __nv_bfloat16 g_y0h[2][SBH],     g_y0l[2][SBH];
__device__ __align__(16) __nv_bfloat16 g_h0h[2][2][BH],   g_h0l[2][2][BH];
__device__ __align__(16) __nv_bfloat16 g_h1h[2][2][BH],   g_h1l[2][2][BH];
__device__ __align__(16) __nv_bfloat16 g_rhh[2][2][BH],   g_rhl[2][2][BH];
__device__ __align__(16) __nv_bfloat16 g_Wh[3][4*HH*IND], g_Wl[3][4*HH*IND]; // [gate r/z/s]

__device__ __forceinline__ float fsig(float x) { return 1.f / (1.f + __expf(-x)); }

__device__ __forceinline__ void bfsplit(float x, __nv_bfloat16& h, __nv_bfloat16& l)
{
    h = __float2bfloat16(x);
    l = __float2bfloat16(x - __bfloat162float(h));
}

__device__ __forceinline__ unsigned smem_u32(const void* p)
{
    return (unsigned)__cvta_generic_to_shared(p);
}

// ---------------- mma / ldmatrix wrappers ----------------
__device__ __forceinline__ void mma_bf16(float* c, const unsigned* a, const unsigned* b)
{
    asm volatile(
        "mma.sync.aligned.m16n8k16.row.col.f32.bf16.bf16.f32 "
        "{%0,%1,%2,%3},{%4,%5,%6,%7},{%8,%9},{%0,%1,%2,%3};\n"
        : "+f"(c[0]), "+f"(c[1]), "+f"(c[2]), "+f"(c[3])
        : "r"(a[0]), "r"(a[1]), "r"(a[2]), "r"(a[3]), "r"(b[0]), "r"(b[1]));
}
__device__ __forceinline__ void ldsm4(unsigned* r, unsigned addr)
{
    asm volatile("ldmatrix.sync.aligned.m8n8.x4.shared.b16 {%0,%1,%2,%3},[%4];\n"
        : "=r"(r[0]), "=r"(r[1]), "=r"(r[2]), "=r"(r[3]) : "r"(addr));
}
__device__ __forceinline__ void ldsm2(unsigned* r, unsigned addr)
{
    asm volatile("ldmatrix.sync.aligned.m8n8.x2.shared.b16 {%0,%1},[%2];\n"
        : "=r"(r[0]), "=r"(r[1]) : "r"(addr));
}

// ---------------- grid-wide spin barrier ----------------
__device__ __forceinline__ void grid_bar(unsigned target)
{
    __threadfence();
    __syncthreads();
    if (threadIdx.x == 0) {
        atomicAdd(&g_bar, 1u);
        while (atomicAdd(&g_bar, 0u) < target)
            __nanosleep(128);
        __threadfence();   // acquire + L1 invalidate
    }
    __syncthreads();
}

// ---------------- embedding gather: write split x, reset barrier ----------------
__global__ void embed_kernel(const int* __restrict__ tok,
                             const float* __restrict__ emb)
{
    if (blockIdx.x == 0 && threadIdx.x == 0) g_bar = 0u;
    int row = blockIdx.x;
    int t = tok[row];
    float4 v = ((const float4*)(emb + (size_t)t * HH))[threadIdx.x];
    size_t base = (size_t)row * HH + threadIdx.x * 4;
    float xs[4] = {v.x, v.y, v.z, v.w};
    #pragma unroll
    for (int j = 0; j < 4; ++j)
        bfsplit(xs[j], g_xh[base + j], g_xl[base + j]);
}

__global__ void init_kernel()
{
    int i = blockIdx.x * blockDim.x + threadIdx.x;
    if (i < BH) {
        __nv_bfloat16 zb = __float2bfloat16(0.f);
        g_h0[0][0][i] = 0.f; g_h0[1][0][i] = 0.f;
        g_h1[0][0][i] = 0.f; g_h1[1][0][i] = 0.f;
        g_h0h[0][0][i] = zb; g_h0h[1][0][i] = zb;
        g_h0l[0][0][i] = zb; g_h0l[1][0][i] = zb;
        g_h1h[0][0][i] = zb; g_h1h[1][0][i] = zb;
        g_h1l[0][0][i] = zb; g_h1l[1][0][i] = zb;
    }
}

// ---------------- one-time: split all weights into bf16 hi/lo ----------------
__global__ void wsplit_kernel(const float* __restrict__ Wr,
                              const float* __restrict__ Wz,
                              const float* __restrict__ Wsv)
{
    int g = blockIdx.y;
    size_t i = (size_t)blockIdx.x * blockDim.x + threadIdx.x;   // 0 .. 2M-1
    const float* src = (g == 0) ? Wr : (g == 1) ? Wz : Wsv;
    bfsplit(src[i], g_Wh[g][i], g_Wl[g][i]);
}

// ---------------- shared tile buffer (single, 27648 B) ----------------
struct SmemM {
    __nv_bfloat16 Ah[64 * LDA];
    __nv_bfloat16 Al[64 * LDA];
    __nv_bfloat16 Wh[32 * LDA];
    __nv_bfloat16 Wl[32 * LDA];
};

// C[64x32] += A[64xK] * W[32xK]^T via split-bf16 mma, 3 products per k16.
// A row stride HH (bf16 hi/lo), W row stride IND with k offset wk0.
__device__ __forceinline__ void gemm_mma(
    const __nv_bfloat16* Ahg, const __nv_bfloat16* Alg,
    const __nv_bfloat16* Whg, const __nv_bfloat16* Wlg,
    int wk0, int c0, int nk,
    float (&acc)[2][2][4], SmemM* sm)
{
    const int tid  = threadIdx.x;
    const int lane = tid & 31;
    const int wid  = tid >> 5;
    const int wm   = (wid & 1) * 32;       // warp row base
    const int wn   = (wid >> 1) * 16;      // warp col base

    const unsigned sAh = smem_u32(sm->Ah);
    const unsigned sAl = smem_u32(sm->Al);
    const unsigned sWh = smem_u32(sm->Wh);
    const unsigned sWl = smem_u32(sm->Wl);
    // ldmatrix per-lane offsets (bytes)
    const unsigned aOff = (unsigned)((lane & 15) * (LDA * 2) + (lane >> 4) * 16);
    const unsigned bOff = (unsigned)((lane & 7)  * (LDA * 2) + ((lane >> 3) & 1) * 16);

    uint4 pa[8], pw[4];
    // prefetch chunk 0
    #pragma unroll
    for (int i = 0; i < 4; ++i) {
        int q = i * 128 + tid, m = q >> 3, k8 = q & 7;
        pa[i]     = *(const uint4*)(Ahg + (size_t)m * HH + k8 * 8);
        pa[i + 4] = *(const uint4*)(Alg + (size_t)m * HH + k8 * 8);
    }
    #pragma unroll
    for (int i = 0; i < 2; ++i) {
        int q = i * 128 + tid, cW = q >> 3, k8 = q & 7;
        pw[i]     = *(const uint4*)(Whg + (size_t)(c0 + cW) * IND + wk0 + k8 * 8);
        pw[i + 2] = *(const uint4*)(Wlg + (size_t)(c0 + cW) * IND + wk0 + k8 * 8);
    }

    for (int k0 = 0; k0 < nk; k0 += 64) {
        __syncthreads();
        #pragma unroll
        for (int i = 0; i < 4; ++i) {
            int q = i * 128 + tid, m = q >> 3, k8 = q & 7;
            *(uint4*)(sm->Ah + m * LDA + k8 * 8) = pa[i];
            *(uint4*)(sm->Al + m * LDA + k8 * 8) = pa[i + 4];
        }
        #pragma unroll
        for (int i = 0; i < 2; ++i) {
            int q = i * 128 + tid, cW = q >> 3, k8 = q & 7;
            *(uint4*)(sm->Wh + cW * LDA + k8 * 8) = pw[i];
            *(uint4*)(sm->Wl + cW * LDA + k8 * 8) = pw[i + 2];
        }
        __syncthreads();
        if (k0 + 64 < nk) {
            int k1 = k0 + 64;
            #pragma unroll
            for (int i = 0; i < 4; ++i) {
                int q = i * 128 + tid, m = q >> 3, k8 = q & 7;
                pa[i]     = *(const uint4*)(Ahg + (size_t)m * HH + k1 + k8 * 8);
                pa[i + 4] = *(const uint4*)(Alg + (size_t)m * HH + k1 + k8 * 8);
            }
            #pragma unroll
            for (int i = 0; i < 2; ++i) {
                int q = i * 128 + tid, cW = q >> 3, k8 = q & 7;
                pw[i]     = *(const uint4*)(Whg + (size_t)(c0 + cW) * IND + wk0 + k1 + k8 * 8);
                pw[i + 2] = *(const uint4*)(Wlg + (size_t)(c0 + cW) * IND + wk0 + k1 + k8 * 8);
            }
        }
        #pragma unroll
        for (int k16 = 0; k16 < 4; ++k16) {
            unsigned ko = k16 * 32;   // 16 bf16 = 32 B
            unsigned ah0[4], ah1[4], al0[4], al1[4];
            unsigned bh0[2], bh1[2], bl0[2], bl1[2];
            ldsm4(ah0, sAh + (wm     ) * (LDA * 2) + aOff + ko);
            ldsm4(ah1, sAh + (wm + 16) * (LDA * 2) + aOff + ko);
            ldsm4(al0, sAl + (wm     ) * (LDA * 2) + aOff + ko);
            ldsm4(al1, sAl + (wm + 16) * (LDA * 2) + aOff + ko);
            ldsm2(bh0, sWh + (wn    ) * (LDA * 2) + bOff + ko);
            ldsm2(bh1, sWh + (wn + 8) * (LDA * 2) + bOff + ko);
            ldsm2(bl0, sWl + (wn    ) * (LDA * 2) + bOff + ko);
            ldsm2(bl1, sWl + (wn + 8) * (LDA * 2) + bOff + ko);
            mma_bf16(acc[0][0], ah0, bh0); mma_bf16(acc[0][0], ah0, bl0); mma_bf16(acc[0][0], al0, bh0);
            mma_bf16(acc[0][1], ah0, bh1); mma_bf16(acc[0][1], ah0, bl1); mma_bf16(acc[0][1], al0, bh1);
            mma_bf16(acc[1][0], ah1, bh0); mma_bf16(acc[1][0], ah1, bl0); mma_bf16(acc[1][0], al1, bh0);
            mma_bf16(acc[1][1], ah1, bh1); mma_bf16(acc[1][1], ah1, bl1); mma_bf16(acc[1][1], al1, bh1);
        }
    }
}

__device__ __forceinline__ void store_acc_mma(float* dst, int c0, float (&acc)[2][2][4])
{
    int lane = threadIdx.x & 31, wid = threadIdx.x >> 5;
    int wm = (wid & 1) * 32, wn = (wid >> 1) * 16;
    int r = lane >> 2, cc = (lane & 3) * 2;
    #pragma unroll
    for (int mt = 0; mt < 2; ++mt)
        #pragma unroll
        for (int nt = 0; nt < 2; ++nt) {
            int row = wm + mt * 16 + r;
            int col = c0 + wn + nt * 8 + cc;
            float2 lo = make_float2(acc[mt][nt][0], acc[mt][nt][1]);
            float2 hi = make_float2(acc[mt][nt][2], acc[mt][nt][3]);
            *(float2*)(dst + (size_t)row * HH + col)       = lo;
            *(float2*)(dst + (size_t)(row + 8) * HH + col) = hi;
        }
}

// ---------------- one-time: L0 input-half preactivations, all timesteps ----------------
__global__ void __launch_bounds__(128)
pre_kernel()
{
    __shared__ SmemM sm;
    int bid  = blockIdx.x;
    int job  = bid >> 12;            // 0..5
    int d    = job / 3;
    int gate = job % 3;
    int rem  = bid & 4095;
    int rowt = rem >> 4;             // 0..255
    int tile = rem & 15;

    const __nv_bfloat16* Ah = g_xh + (size_t)rowt * 64 * HH;
    const __nv_bfloat16* Al = g_xl + (size_t)rowt * 64 * HH;
    const __nv_bfloat16* Wh = g_Wh[gate] + (size_t)(d * 2 + 0) * HH * IND;
    const __nv_bfloat16* Wl = g_Wl[gate] + (size_t)(d * 2 + 0) * HH * IND;

    float acc[2][2][4] = {};
    gemm_mma(Ah, Al, Wh, Wl, 0, tile * 32, HH, acc, &sm);
    store_acc_mma(g_pin[d][gate] + (size_t)rowt * 64 * HH, tile * 32, acc);
}

// ---------------- the persistent recurrence kernel ----------------
__global__ void __launch_bounds__(128, 4)
persist_kernel(const float* __restrict__ br, const float* __restrict__ bz,
               const float* __restrict__ bsv, float* __restrict__ dout)
{
    __shared__ SmemM sm;
    const int bid = blockIdx.x;
    const int tid = threadIdx.x;
    const int gtid = bid * 128 + tid;
    unsigned tgt = 0;

    for (int t = 0; t <= SQ; ++t) {
        // ================= P1: r/z GEMM slices + L1 s-input (all K=256) =================
        {
            const __nv_bfloat16 *Ah = 0, *Al = 0, *Wh = 0, *Wl = 0;
            float* dst = 0;
            int wk0 = 0, tile = 0, active = 0;
            if (bid < 128) {                        // L0 r/z recurrent
                if (t < SQ) {
                    int d     = (bid >> 6) & 1;
                    int gate  = (bid >> 5) & 1;
                    int slice = (bid >> 4) & 1;
                    tile      =  bid       & 15;
                    Ah = g_h0h[d][t & 1] + slice * 256;
                    Al = g_h0l[d][t & 1] + slice * 256;
                    Wh = g_Wh[gate] + (size_t)(d * 2 + 0) * HH * IND;
                    Wl = g_Wl[gate] + (size_t)(d * 2 + 0) * HH * IND;
                    wk0 = HH + slice * 256;
                    dst = g_paL0[d][gate][slice];
                    active = 1;
                }
            } else if (bid < 384) {                 // L1 r/z, K=1024 in 4 slices
                if (t >= 1) {
                    int q     = bid - 128;
                    int d     = (q >> 7) & 1;
                    int gate  = (q >> 6) & 1;
                    int slice = (q >> 4) & 3;
                    tile      =  q       & 15;
                    int u = t - 1;
                    if (slice < 2) {
                        Ah = g_y0h[d] + (size_t)u * BH + slice * 256;
                        Al = g_y0l[d] + (size_t)u * BH + slice * 256;
                    } else {
                        Ah = g_h1h[d][u & 1] + (slice - 2) * 256;
                        Al = g_h1l[d][u & 1] + (slice - 2) * 256;
                    }
                    Wh = g_Wh[gate] + (size_t)(d * 2 + 1) * HH * IND;
                    Wl = g_Wl[gate] + (size_t)(d * 2 + 1) * HH * IND;
                    wk0 = slice * 256;
                    dst = g_paL1[d][gate][slice];
                    active = 1;
                }
            } else {                                // L1 s-input, K=512 in 2 slices
                if (t >= 1) {
                    int q     = bid - 384;
                    int d     = (q >> 5) & 1;
                    int slice = (q >> 4) & 1;
                    tile      =  q       & 15;
                    int u = t - 1;
                    Ah = g_y0h[d] + (size_t)u * BH + slice * 256;
                    Al = g_y0l[d] + (size_t)u * BH + slice * 256;
                    Wh = g_Wh[2] + (size_t)(d * 2 + 1) * HH * IND;
                    Wl = g_Wl[2] + (size_t)(d * 2 + 1) * HH * IND;
                    wk0 = slice * 256;
                    dst = g_psp[d][slice];
                    active = 1;
                }
            }
            if (active) {
                float acc[2][2][4] = {};
                gemm_mma(Ah, Al, Wh, Wl, wk0, tile * 32, 256, acc, &sm);
                store_acc_mma(dst, tile * 32, acc);
            }
        }
        tgt += NBLK; grid_bar(tgt);

        // ================= P2: combA (r sigmoid + r*h split, z sigmoid) =================
        for (int e = gtid; e < 4 * BH; e += NBLK * 128) {
            int cell  = e >> 15;
            int layer = cell >> 1;
            int d     = cell & 1;
            if (layer == 0 && t >= SQ) continue;
            if (layer == 1 && t <  1 ) continue;
            int u   = (layer == 0) ? t : (t - 1);
            int idx = e & (BH - 1);
            int col = idx & 511;

            const float* h = (layer == 0) ? g_h0[d][u & 1] : g_h1[d][u & 1];
            float rpre, zpre;
            if (layer == 0) {
                int rt = d ? (SQ - 1 - t) : t;
                rpre = g_pin[d][0][(size_t)rt * BH + idx]
                     + g_paL0[d][0][0][idx] + g_paL0[d][0][1][idx];
                zpre = g_pin[d][1][(size_t)rt * BH + idx]
                     + g_paL0[d][1][0][idx] + g_paL0[d][1][1][idx];
            } else {
                rpre = g_paL1[d][0][0][idx] + g_paL1[d][0][1][idx]
                     + g_paL1[d][0][2][idx] + g_paL1[d][0][3][idx];
                zpre = g_paL1[d][1][0][idx] + g_paL1[d][1][1][idx]
                     + g_paL1[d][1][2][idx] + g_paL1[d][1][3][idx];
            }
            int boff = (d * 2 + layer) * HH + col;
            float rh = fsig(rpre + br[boff]) * h[idx];
            bfsplit(rh, g_rhh[layer][d][idx], g_rhl[layer][d][idx]);
            g_z[layer][d][idx] = fsig(zpre + bz[boff]);
        }
        tgt += NBLK; grid_bar(tgt);

        // ================= P3: s recurrent GEMM, K=512 in 4 slices =================
        if (bid < 256) {
            int layer = (bid >> 7) & 1;
            int d     = (bid >> 6) & 1;
            int slice = (bid >> 4) & 3;
            int tile  =  bid       & 15;
            int active = !((layer == 0 && t >= SQ) || (layer == 1 && t < 1));
            if (active) {
                const __nv_bfloat16* Ah = g_rhh[layer][d] + slice * 128;
                const __nv_bfloat16* Al = g_rhl[layer][d] + slice * 128;
                const __nv_bfloat16* Wh = g_Wh[2] + (size_t)(d * 2 + layer) * HH * IND;
                const __nv_bfloat16* Wl = g_Wl[2] + (size_t)(d * 2 + layer) * HH * IND;
                float acc[2][2][4] = {};
                gemm_mma(Ah, Al, Wh, Wl, HH + slice * 128, tile * 32, 128, acc, &sm);
                store_acc_mma(g_sp[layer][d][slice], tile * 32, acc);
            }
        }
        tgt += NBLK; grid_bar(tgt);

        // ================= P4: combS (tanh + mix + h update + splits + outputs) =================
        for (int e = gtid; e < 4 * BH; e += NBLK * 128) {
            int cell  = e >> 15;
            int layer = cell >> 1;
            int d     = cell & 1;
            if (layer == 0 && t >= SQ) continue;
            if (layer == 1 && t <  1 ) continue;
            int u   = (layer == 0) ? t : (t - 1);
            int idx = e & (BH - 1);
            int m   = idx >> 9;
            int col = idx & 511;

            float pre;
            if (layer == 0) {
                int rt = d ? (SQ - 1 - t) : t;
                pre = g_pin[d][2][(size_t)rt * BH + idx];
            } else {
                pre = g_psp[d][0][idx] + g_psp[d][1][idx];
            }
            pre += bsv[(d * 2 + layer) * HH + col];
            pre += g_sp[layer][d][0][idx] + g_sp[layer][d][1][idx]
                 + g_sp[layer][d][2][idx] + g_sp[layer][d][3][idx];

            float s = tanhf(pre);
            float z = g_z[layer][d][idx];

            const float* hp = (layer == 0) ? g_h0[d][u & 1]       : g_h1[d][u & 1];
            float*       hn = (layer == 0) ? g_h0[d][(u + 1) & 1] : g_h1[d][(u + 1) & 1];

            float h = z * hp[idx] + (1.f - z) * s;
            hn[idx] = h;
            if (layer == 0) {
                bfsplit(h, g_h0h[d][(u + 1) & 1][idx], g_h0l[d][(u + 1) & 1][idx]);
                bfsplit(h, g_y0h[d][(size_t)u * BH + idx], g_y0l[d][(size_t)u * BH + idx]);
                if (u == SQ - 1)
                    dout[OUT_SZ + (size_t)(d * 2 + 0) * BH + idx] = h;
            } else {
                bfsplit(h, g_h1h[d][(u + 1) & 1][idx], g_h1l[d][(u + 1) & 1][idx]);
                dout[(size_t)u * BB * (2 * HH) + (size_t)m * (2 * HH) + d * HH + col] = h;
                if (u == SQ - 1)
                    dout[OUT_SZ + (size_t)(d * 2 + 1) * BH + idx] = h;
            }
        }
        tgt += NBLK; grid_bar(tgt);
    }
}

// ---------------- launcher: 5 graph nodes ----------------
extern "C" void kernel_launch(void* const* d_in, const int* in_sizes, int n_in,
                              void* d_out, int out_size)
{
    const int*   tok = (const int*)  d_in[0];
    const float* emb = (const float*)d_in[1];
    const float* Wr  = (const float*)d_in[2];
    const float* Wz  = (const float*)d_in[3];
    const float* Wsv = (const float*)d_in[4];
    const float* br  = (const float*)d_in[5];
    const float* bz  = (const float*)d_in[6];
    const float* bsv = (const float*)d_in[7];
    float* outp = (float*)d_out;

    embed_kernel<<<SQ * BB, 128>>>(tok, emb);
    init_kernel<<<(BH + 255) / 256, 256>>>();
    {
        dim3 g((4 * HH * IND) / 256, 3);
        wsplit_kernel<<<g, 256>>>(Wr, Wz, Wsv);
    }
    pre_kernel<<<24576, 128>>>();
    persist_kernel<<<NBLK, 128>>>(br, bz, bsv, outp);
}